// round 6
// baseline (speedup 1.0000x reference)
#include <cuda_runtime.h>
#include <cuda_bf16.h>

#define NROWS 8192

__device__ float        g_partials[NROWS];
__device__ unsigned int g_done = 0;

typedef unsigned long long u64;

// Pack two f32 regs into a b64 pair — exact pattern from ptx_helpers.cuh PACK_F32X2.
__device__ __forceinline__ u64 pk2(float lo, float hi) {
    u64 r;
    asm("mov.b64 %0, {%1, %2};" : "=l"(r) : "f"(lo), "f"(hi));
    return r;
}
__device__ __forceinline__ void upk2(u64 v, float& lo, float& hi) {
    asm("mov.b64 {%0, %1}, %2;" : "=f"(lo), "=f"(hi) : "l"(v));
}
__device__ __forceinline__ u64 ffma2(u64 a, u64 b, u64 c) {
    u64 d;
    asm("fma.rn.f32x2 %0, %1, %2, %3;" : "=l"(d) : "l"(a), "l"(b), "l"(c));
    return d;
}
__device__ __forceinline__ u64 fmul2(u64 a, u64 b) {
    u64 d;
    asm("mul.rn.f32x2 %0, %1, %2;" : "=l"(d) : "l"(a), "l"(b));
    return d;
}
__device__ __forceinline__ u64 fadd2(u64 a, u64 b) {
    u64 d;
    asm("add.rn.f32x2 %0, %1, %2;" : "=l"(d) : "l"(a), "l"(b));
    return d;
}
__device__ __forceinline__ float ex2a(float x) {
    float y;
    asm("ex2.approx.f32 %0, %1;" : "=f"(y) : "f"(x));
    return y;
}

__global__ __launch_bounds__(256) void bce_kernel(
    const float* __restrict__ x,
    const int* __restrict__ tg32,   // int64 targets viewed as int pairs (LE low word)
    float* __restrict__ out,
    int N, float inv_count)
{
    const int row = blockIdx.x;
    const int t   = tg32[row * 2];
    const int q   = t >> 2;         // boundary float4 index
    const int r   = t & 3;
    const int n4  = N >> 2;

    const float4* __restrict__ xr =
        reinterpret_cast<const float4*>(x + (size_t)row * N);

    // log1p(y) on [0,1]: A&S 4.1.43 degree-5 poly, |err| <= 1e-5
    const u64 C0   = pk2( 0.99949556f,  0.99949556f);
    const u64 C1   = pk2(-0.49190896f, -0.49190896f);
    const u64 C2   = pk2( 0.28947478f,  0.28947478f);
    const u64 C3   = pk2(-0.13606275f, -0.13606275f);
    const u64 C4   = pk2( 0.03215845f,  0.03215845f);
    const u64 NL2E = pk2(-1.4426950408889634f, -1.4426950408889634f);
    const u64 HALF = pk2(0.5f, 0.5f);
    const u64 ABSM = 0x7FFFFFFF7FFFFFFFULL;

    u64 accP0 = 0ULL, accP1 = 0ULL;  // log1p-poly accumulators
    u64 accM0 = 0ULL, accM1 = 0ULL;  // relu(x) accumulators
    u64 accS0 = 0ULL, accS1 = 0ULL;  // masked-subtract accumulators
    float sFix = 0.0f;               // boundary-quad correction (rare)

    #pragma unroll 8
    for (int idx = threadIdx.x; idx < n4; idx += 256) {
        float4 v = xr[idx];
        u64 v01 = pk2(v.x, v.y);
        u64 v23 = pk2(v.z, v.w);
        u64 a01 = v01 & ABSM;
        u64 a23 = v23 & ABSM;
        // exp(-|x|): packed scale + 4x ex2.approx
        u64 u01 = fmul2(a01, NL2E);
        u64 u23 = fmul2(a23, NL2E);
        float e0, e1, e2, e3;
        upk2(u01, e0, e1); upk2(u23, e2, e3);
        u64 y01 = pk2(ex2a(e0), ex2a(e1));
        u64 y23 = pk2(ex2a(e2), ex2a(e3));
        // log1p poly; final FMA folds into accumulator
        u64 p01 = ffma2(y01, C4, C3);
        p01 = ffma2(y01, p01, C2);
        p01 = ffma2(y01, p01, C1);
        p01 = ffma2(y01, p01, C0);
        accP0 = ffma2(y01, p01, accP0);
        u64 p23 = ffma2(y23, C4, C3);
        p23 = ffma2(y23, p23, C2);
        p23 = ffma2(y23, p23, C1);
        p23 = ffma2(y23, p23, C0);
        accP1 = ffma2(y23, p23, accP1);
        // relu(x) = 0.5*(x+|x|), exact, fully packed
        accM0 = ffma2(fadd2(v01, a01), HALF, accM0);
        accM1 = ffma2(fadd2(v23, a23), HALF, accM1);
        // target-prefix subtraction: whole quads via packed adds
        if (idx < q) {
            accS0 = fadd2(accS0, v01);
            accS1 = fadd2(accS1, v23);
        } else if (idx == q && r > 0) {
            // partial boundary quad: use registers already in hand
            float sub = v.x;
            if (r > 1) sub += v.y;
            if (r > 2) sub += v.z;
            sFix += sub;
        }
    }

    float s;
    {
        float pa, pb, pc, pd, ma, mb, mc, md, sa, sb, sc, sd;
        upk2(accP0, pa, pb); upk2(accP1, pc, pd);
        upk2(accM0, ma, mb); upk2(accM1, mc, md);
        upk2(accS0, sa, sb); upk2(accS1, sc, sd);
        s = ((pa + pb) + (pc + pd)) + ((ma + mb) + (mc + md))
          - ((sa + sb) + (sc + sd)) - sFix;
    }

    // ---- block reduction (8 warps) ----
    #pragma unroll
    for (int o = 16; o > 0; o >>= 1)
        s += __shfl_xor_sync(0xFFFFFFFFu, s, o);

    __shared__ float warp_sums[8];
    const int lane = threadIdx.x & 31;
    const int wid  = threadIdx.x >> 5;
    if (lane == 0) warp_sums[wid] = s;
    __syncthreads();

    __shared__ bool is_last;
    if (threadIdx.x < 32) {
        float v = (lane < 8) ? warp_sums[lane] : 0.0f;
        #pragma unroll
        for (int o = 4; o > 0; o >>= 1)
            v += __shfl_xor_sync(0xFFFFFFFFu, v, o);
        if (lane == 0) {
            g_partials[blockIdx.x] = v;
            __threadfence();
            unsigned int ticket = atomicAdd(&g_done, 1u);
            is_last = (ticket == gridDim.x - 1);
        }
    }
    __syncthreads();

    // ---- last block: tail reduction over all partials ----
    if (is_last) {
        __threadfence();  // acquire: order partial reads after ticket observation
        float d = 0.0f;
        for (int i = threadIdx.x; i < (int)gridDim.x; i += 256)
            d += g_partials[i];

        #pragma unroll
        for (int o = 16; o > 0; o >>= 1)
            d += __shfl_xor_sync(0xFFFFFFFFu, d, o);

        if (lane == 0) warp_sums[wid] = d;
        __syncthreads();

        if (threadIdx.x < 32) {
            float v = (lane < 8) ? warp_sums[lane] : 0.0f;
            #pragma unroll
            for (int o = 4; o > 0; o >>= 1)
                v += __shfl_xor_sync(0xFFFFFFFFu, v, o);
            if (lane == 0) {
                out[0] = v * inv_count;
                g_done = 0;   // reset for next graph replay
            }
        }
    }
}

extern "C" void kernel_launch(void* const* d_in, const int* in_sizes, int n_in,
                              void* d_out, int out_size)
{
    const float* x    = (const float*)d_in[0];
    const int*   tg32 = (const int*)d_in[1];
    float* out = (float*)d_out;

    const int B = in_sizes[1];
    const int N = in_sizes[0] / B;

    const float inv_count = (float)(1.0 / ((double)B * (double)N));
    bce_kernel<<<B, 256>>>(x, tg32, out, N, inv_count);
}

// round 7
// speedup vs baseline: 1.0821x; 1.0821x over previous
#include <cuda_runtime.h>
#include <cuda_bf16.h>

#define NROWS 8192

__device__ float        g_partials[NROWS];
__device__ unsigned int g_done = 0;

typedef unsigned long long u64;

__device__ __forceinline__ u64 pk2(float lo, float hi) {
    u64 r;
    asm("mov.b64 %0, {%1, %2};" : "=l"(r) : "f"(lo), "f"(hi));
    return r;
}
__device__ __forceinline__ void upk2(u64 v, float& lo, float& hi) {
    asm("mov.b64 {%0, %1}, %2;" : "=f"(lo), "=f"(hi) : "l"(v));
}
__device__ __forceinline__ u64 ffma2(u64 a, u64 b, u64 c) {
    u64 d;
    asm("fma.rn.f32x2 %0, %1, %2, %3;" : "=l"(d) : "l"(a), "l"(b), "l"(c));
    return d;
}
__device__ __forceinline__ u64 fmul2(u64 a, u64 b) {
    u64 d;
    asm("mul.rn.f32x2 %0, %1, %2;" : "=l"(d) : "l"(a), "l"(b));
    return d;
}
__device__ __forceinline__ u64 fadd2(u64 a, u64 b) {
    u64 d;
    asm("add.rn.f32x2 %0, %1, %2;" : "=l"(d) : "l"(a), "l"(b));
    return d;
}
__device__ __forceinline__ float ex2a(float x) {
    float y;
    asm("ex2.approx.f32 %0, %1;" : "=f"(y) : "f"(x));
    return y;
}

__global__ __launch_bounds__(256) void bce_kernel(
    const float* __restrict__ x,
    const int* __restrict__ tg32,   // int64 targets viewed as int pairs (LE low word)
    float* __restrict__ out,
    int N, float inv_count)
{
    const int row = blockIdx.x;
    const int t   = tg32[row * 2];
    const int q   = t >> 2;         // boundary float4 index
    const int r   = t & 3;
    const int n4  = N >> 2;

    const float4* __restrict__ xr =
        reinterpret_cast<const float4*>(x + (size_t)row * N);

    // log1p(y) on [0,1]: A&S 4.1.43 degree-5 poly, |err| <= 1e-5
    const u64 C0   = pk2( 0.99949556f,  0.99949556f);
    const u64 C1   = pk2(-0.49190896f, -0.49190896f);
    const u64 C2   = pk2( 0.28947478f,  0.28947478f);
    const u64 C3   = pk2(-0.13606275f, -0.13606275f);
    const u64 C4   = pk2( 0.03215845f,  0.03215845f);
    const u64 NL2E = pk2(-1.4426950408889634f, -1.4426950408889634f);
    const u64 SGN2 = 0x8000000080000000ULL;

    u64 accP0 = 0ULL, accP1 = 0ULL;  // log1p-poly sums
    u64 accA0 = 0ULL, accA1 = 0ULL;  // |x| sums
    u64 accV0 = 0ULL, accV1 = 0ULL;  // sign-folded x sums (+x if j>=t, -x if j<t)
    float sFix = 0.0f;               // partial boundary-quad correction

    if (n4 == 2048) {
        // Phase 1: unconditional front-batched loads (MLP = 8)
        float4 vv[8];
        #pragma unroll
        for (int k = 0; k < 8; k++)
            vv[k] = xr[threadIdx.x + (k << 8)];

        // Phase 2: compute
        #pragma unroll
        for (int k = 0; k < 8; k++) {
            const int idx = threadIdx.x + (k << 8);
            const float4 v = vv[k];
            const float a0 = fabsf(v.x), a1 = fabsf(v.y);
            const float a2 = fabsf(v.z), a3 = fabsf(v.w);
            const u64 a01 = pk2(a0, a1), a23 = pk2(a2, a3);
            // exp(-|x|)
            const u64 u01 = fmul2(a01, NL2E);
            const u64 u23 = fmul2(a23, NL2E);
            float e0, e1, e2, e3;
            upk2(u01, e0, e1); upk2(u23, e2, e3);
            const u64 y01 = pk2(ex2a(e0), ex2a(e1));
            const u64 y23 = pk2(ex2a(e2), ex2a(e3));
            // log1p poly; final FMA folds into accumulator
            u64 p01 = ffma2(y01, C4, C3);
            p01 = ffma2(y01, p01, C2);
            p01 = ffma2(y01, p01, C1);
            p01 = ffma2(y01, p01, C0);
            accP0 = ffma2(y01, p01, accP0);
            u64 p23 = ffma2(y23, C4, C3);
            p23 = ffma2(y23, p23, C2);
            p23 = ffma2(y23, p23, C1);
            p23 = ffma2(y23, p23, C0);
            accP1 = ffma2(y23, p23, accP1);
            // |x| sums
            accA0 = fadd2(accA0, a01);
            accA1 = fadd2(accA1, a23);
            // sign-folded x sums (branch-free: SEL + XOR)
            const u64 flip = (idx < q) ? SGN2 : 0ULL;
            accV0 = fadd2(accV0, pk2(v.x, v.y) ^ flip);
            accV1 = fadd2(accV1, pk2(v.z, v.w) ^ flip);
            // partial boundary quad: correct first r elements of quad q
            if (idx == q && r > 0) {
                float c = v.x;
                if (r > 1) c += v.y;
                if (r > 2) c += v.z;
                sFix = c;
            }
        }
    } else {
        // generic fallback (correctness path)
        for (int idx = threadIdx.x; idx < n4; idx += 256) {
            const float4 v = xr[idx];
            const float a0 = fabsf(v.x), a1 = fabsf(v.y);
            const float a2 = fabsf(v.z), a3 = fabsf(v.w);
            const u64 a01 = pk2(a0, a1), a23 = pk2(a2, a3);
            const u64 u01 = fmul2(a01, NL2E);
            const u64 u23 = fmul2(a23, NL2E);
            float e0, e1, e2, e3;
            upk2(u01, e0, e1); upk2(u23, e2, e3);
            const u64 y01 = pk2(ex2a(e0), ex2a(e1));
            const u64 y23 = pk2(ex2a(e2), ex2a(e3));
            u64 p01 = ffma2(y01, C4, C3);
            p01 = ffma2(y01, p01, C2);
            p01 = ffma2(y01, p01, C1);
            p01 = ffma2(y01, p01, C0);
            accP0 = ffma2(y01, p01, accP0);
            u64 p23 = ffma2(y23, C4, C3);
            p23 = ffma2(y23, p23, C2);
            p23 = ffma2(y23, p23, C1);
            p23 = ffma2(y23, p23, C0);
            accP1 = ffma2(y23, p23, accP1);
            accA0 = fadd2(accA0, a01);
            accA1 = fadd2(accA1, a23);
            const u64 flip = (idx < q) ? SGN2 : 0ULL;
            accV0 = fadd2(accV0, pk2(v.x, v.y) ^ flip);
            accV1 = fadd2(accV1, pk2(v.z, v.w) ^ flip);
            if (idx == q && r > 0) {
                float c = v.x;
                if (r > 1) c += v.y;
                if (r > 2) c += v.z;
                sFix = c;
            }
        }
    }

    // s = sum( 0.5*(|x| + sign*x) + log1p(exp(-|x|)) ) - boundary_fix
    float s;
    {
        float pa, pb, pc, pd, aa, ab, ac, ad, va, vb, vc, vd;
        upk2(accP0, pa, pb); upk2(accP1, pc, pd);
        upk2(accA0, aa, ab); upk2(accA1, ac, ad);
        upk2(accV0, va, vb); upk2(accV1, vc, vd);
        const float A = (aa + ab) + (ac + ad);
        const float V = (va + vb) + (vc + vd);
        const float P = (pa + pb) + (pc + pd);
        s = 0.5f * (A + V) + P - sFix;
    }

    // ---- block reduction (8 warps) ----
    #pragma unroll
    for (int o = 16; o > 0; o >>= 1)
        s += __shfl_xor_sync(0xFFFFFFFFu, s, o);

    __shared__ float warp_sums[8];
    const int lane = threadIdx.x & 31;
    const int wid  = threadIdx.x >> 5;
    if (lane == 0) warp_sums[wid] = s;
    __syncthreads();

    __shared__ bool is_last;
    if (threadIdx.x < 32) {
        float v = (lane < 8) ? warp_sums[lane] : 0.0f;
        #pragma unroll
        for (int o = 4; o > 0; o >>= 1)
            v += __shfl_xor_sync(0xFFFFFFFFu, v, o);
        if (lane == 0) {
            g_partials[blockIdx.x] = v;
            __threadfence();
            unsigned int ticket = atomicAdd(&g_done, 1u);
            is_last = (ticket == gridDim.x - 1);
        }
    }
    __syncthreads();

    // ---- last block: tail reduction over all partials ----
    if (is_last) {
        __threadfence();
        float d = 0.0f;
        for (int i = threadIdx.x; i < (int)gridDim.x; i += 256)
            d += g_partials[i];

        #pragma unroll
        for (int o = 16; o > 0; o >>= 1)
            d += __shfl_xor_sync(0xFFFFFFFFu, d, o);

        if (lane == 0) warp_sums[wid] = d;
        __syncthreads();

        if (threadIdx.x < 32) {
            float v = (lane < 8) ? warp_sums[lane] : 0.0f;
            #pragma unroll
            for (int o = 4; o > 0; o >>= 1)
                v += __shfl_xor_sync(0xFFFFFFFFu, v, o);
            if (lane == 0) {
                out[0] = v * inv_count;
                g_done = 0;   // reset for next graph replay
            }
        }
    }
}

extern "C" void kernel_launch(void* const* d_in, const int* in_sizes, int n_in,
                              void* d_out, int out_size)
{
    const float* x    = (const float*)d_in[0];
    const int*   tg32 = (const int*)d_in[1];
    float* out = (float*)d_out;

    const int B = in_sizes[1];
    const int N = in_sizes[0] / B;

    const float inv_count = (float)(1.0 / ((double)B * (double)N));
    bce_kernel<<<B, 256>>>(x, tg32, out, N, inv_count);
}

// round 8
// speedup vs baseline: 1.2598x; 1.1642x over previous
#include <cuda_runtime.h>
#include <cuda_bf16.h>
#include <cstdint>

#define NROWS 8192

__device__ float        g_partials[NROWS];
__device__ unsigned int g_done = 0;

typedef unsigned long long u64;

__device__ __forceinline__ u64 pk2(float lo, float hi) {
    u64 r;
    asm("mov.b64 %0, {%1, %2};" : "=l"(r) : "f"(lo), "f"(hi));
    return r;
}
__device__ __forceinline__ void upk2(u64 v, float& lo, float& hi) {
    asm("mov.b64 {%0, %1}, %2;" : "=f"(lo), "=f"(hi) : "l"(v));
}
__device__ __forceinline__ u64 ffma2(u64 a, u64 b, u64 c) {
    u64 d;
    asm("fma.rn.f32x2 %0, %1, %2, %3;" : "=l"(d) : "l"(a), "l"(b), "l"(c));
    return d;
}
__device__ __forceinline__ u64 fmul2(u64 a, u64 b) {
    u64 d;
    asm("mul.rn.f32x2 %0, %1, %2;" : "=l"(d) : "l"(a), "l"(b));
    return d;
}
__device__ __forceinline__ u64 fadd2(u64 a, u64 b) {
    u64 d;
    asm("add.rn.f32x2 %0, %1, %2;" : "=l"(d) : "l"(a), "l"(b));
    return d;
}
__device__ __forceinline__ float ex2a(float x) {
    float y;
    asm("ex2.approx.f32 %0, %1;" : "=f"(y) : "f"(x));
    return y;
}
__device__ __forceinline__ uint32_t cvta_s(const void* p) {
    uint32_t a;
    asm("{ .reg .u64 t; cvta.to.shared.u64 t, %1; cvt.u32.u64 %0, t; }"
        : "=r"(a) : "l"(p));
    return a;
}
__device__ __forceinline__ void mbar_init(uint32_t mb, uint32_t cnt) {
    asm volatile("mbarrier.init.shared.b64 [%0], %1;" :: "r"(mb), "r"(cnt) : "memory");
}
__device__ __forceinline__ void mbar_expect_tx(uint32_t mb, uint32_t bytes) {
    asm volatile("mbarrier.arrive.expect_tx.shared.b64 _, [%0], %1;"
                 :: "r"(mb), "r"(bytes) : "memory");
}
__device__ __forceinline__ void bulk_g2s(uint32_t dst_smem, const void* src, uint32_t bytes,
                                         uint32_t mb) {
    asm volatile(
        "cp.async.bulk.shared::cluster.global.mbarrier::complete_tx::bytes "
        "[%0], [%1], %2, [%3];"
        :: "r"(dst_smem), "l"(src), "r"(bytes), "r"(mb) : "memory");
}
__device__ __forceinline__ void mbar_wait(uint32_t mb, uint32_t parity) {
    asm volatile(
        "{\n\t.reg .pred P;\n\t"
        "W_%=:\n\t"
        "mbarrier.try_wait.parity.acquire.cta.shared::cta.b64 P, [%0], %1, 0x989680;\n\t"
        "@P bra.uni D_%=;\n\t"
        "bra.uni W_%=;\n\t"
        "D_%=:\n\t}"
        :: "r"(mb), "r"(parity) : "memory");
}

#define STAGE_BYTES 16384
#define STAGE_QUADS 1024

__global__ __launch_bounds__(256) void bce_kernel(
    const float* __restrict__ x,
    const int* __restrict__ tg32,   // int64 targets viewed as int pairs (LE low word)
    float* __restrict__ out,
    int N, float inv_count)
{
    __shared__ __align__(128) float4 sbuf[2 * STAGE_QUADS];   // 32 KB
    __shared__ __align__(8)  unsigned long long mbar_store[2];

    const int row = blockIdx.x;
    const int t   = tg32[row * 2];
    const int q   = t >> 2;         // boundary float4 index
    const int r   = t & 3;
    const int n4  = N >> 2;

    // log1p(y) on [0,1]: A&S 4.1.43 degree-5 poly, |err| <= 1e-5
    const u64 C0   = pk2( 0.99949556f,  0.99949556f);
    const u64 C1   = pk2(-0.49190896f, -0.49190896f);
    const u64 C2   = pk2( 0.28947478f,  0.28947478f);
    const u64 C3   = pk2(-0.13606275f, -0.13606275f);
    const u64 C4   = pk2( 0.03215845f,  0.03215845f);
    const u64 NL2E = pk2(-1.4426950408889634f, -1.4426950408889634f);
    const u64 SGN2 = 0x8000000080000000ULL;

    u64 accP = 0ULL;   // log1p-poly sums
    u64 accA = 0ULL;   // |x| sums
    u64 accV = 0ULL;   // sign-folded x sums
    float sFix = 0.0f; // partial boundary-quad correction

    if (n4 == 2048) {
        const uint32_t smem = cvta_s(sbuf);
        const uint32_t mb0  = cvta_s(&mbar_store[0]);
        const uint32_t mb1  = cvta_s(&mbar_store[1]);
        const char* src = (const char*)(x + (size_t)row * N);

        if (threadIdx.x == 0) {
            mbar_init(mb0, 1);
            mbar_init(mb1, 1);
        }
        __syncthreads();
        if (threadIdx.x == 0) {
            mbar_expect_tx(mb0, STAGE_BYTES);
            bulk_g2s(smem, src, STAGE_BYTES, mb0);
            mbar_expect_tx(mb1, STAGE_BYTES);
            bulk_g2s(smem + STAGE_BYTES, src + STAGE_BYTES, STAGE_BYTES, mb1);
        }

        #pragma unroll
        for (int st = 0; st < 2; st++) {
            mbar_wait(st == 0 ? mb0 : mb1, 0);
            #pragma unroll
            for (int k = 0; k < 4; k++) {
                const int idx = (st << 10) + (int)threadIdx.x + (k << 8);
                const float4 v = sbuf[idx];
                const float a0 = fabsf(v.x), a1 = fabsf(v.y);
                const float a2 = fabsf(v.z), a3 = fabsf(v.w);
                const u64 a01 = pk2(a0, a1), a23 = pk2(a2, a3);
                // exp(-|x|)
                const u64 u01 = fmul2(a01, NL2E);
                const u64 u23 = fmul2(a23, NL2E);
                float e0, e1, e2, e3;
                upk2(u01, e0, e1); upk2(u23, e2, e3);
                const u64 y01 = pk2(ex2a(e0), ex2a(e1));
                const u64 y23 = pk2(ex2a(e2), ex2a(e3));
                // log1p poly; final FMA folds into accumulator
                u64 p01 = ffma2(y01, C4, C3);
                p01 = ffma2(y01, p01, C2);
                p01 = ffma2(y01, p01, C1);
                p01 = ffma2(y01, p01, C0);
                accP = ffma2(y01, p01, accP);
                u64 p23 = ffma2(y23, C4, C3);
                p23 = ffma2(y23, p23, C2);
                p23 = ffma2(y23, p23, C1);
                p23 = ffma2(y23, p23, C0);
                accP = ffma2(y23, p23, accP);
                // |x| sums
                accA = fadd2(accA, fadd2(a01, a23));
                // sign-folded x sums (branch-free)
                const u64 flip = (idx < q) ? SGN2 : 0ULL;
                accV = fadd2(accV, fadd2(pk2(v.x, v.y) ^ flip, pk2(v.z, v.w) ^ flip));
                // partial boundary quad
                if (idx == q && r > 0) {
                    float c = v.x;
                    if (r > 1) c += v.y;
                    if (r > 2) c += v.z;
                    sFix = c;
                }
            }
        }
    } else {
        // generic correctness path (plain global loads)
        const float4* __restrict__ xr =
            reinterpret_cast<const float4*>(x + (size_t)row * N);
        for (int idx = threadIdx.x; idx < n4; idx += 256) {
            const float4 v = xr[idx];
            const float a0 = fabsf(v.x), a1 = fabsf(v.y);
            const float a2 = fabsf(v.z), a3 = fabsf(v.w);
            const u64 a01 = pk2(a0, a1), a23 = pk2(a2, a3);
            const u64 u01 = fmul2(a01, NL2E);
            const u64 u23 = fmul2(a23, NL2E);
            float e0, e1, e2, e3;
            upk2(u01, e0, e1); upk2(u23, e2, e3);
            const u64 y01 = pk2(ex2a(e0), ex2a(e1));
            const u64 y23 = pk2(ex2a(e2), ex2a(e3));
            u64 p01 = ffma2(y01, C4, C3);
            p01 = ffma2(y01, p01, C2);
            p01 = ffma2(y01, p01, C1);
            p01 = ffma2(y01, p01, C0);
            accP = ffma2(y01, p01, accP);
            u64 p23 = ffma2(y23, C4, C3);
            p23 = ffma2(y23, p23, C2);
            p23 = ffma2(y23, p23, C1);
            p23 = ffma2(y23, p23, C0);
            accP = ffma2(y23, p23, accP);
            accA = fadd2(accA, fadd2(a01, a23));
            const u64 flip = (idx < q) ? SGN2 : 0ULL;
            accV = fadd2(accV, fadd2(pk2(v.x, v.y) ^ flip, pk2(v.z, v.w) ^ flip));
            if (idx == q && r > 0) {
                float c = v.x;
                if (r > 1) c += v.y;
                if (r > 2) c += v.z;
                sFix = c;
            }
        }
    }

    // s = sum( 0.5*(|x| + sign*x) + log1p(exp(-|x|)) ) - boundary_fix
    float s;
    {
        float pa, pb, aa, ab, va, vb;
        upk2(accP, pa, pb);
        upk2(accA, aa, ab);
        upk2(accV, va, vb);
        s = 0.5f * ((aa + ab) + (va + vb)) + (pa + pb) - sFix;
    }

    // ---- block reduction (8 warps) ----
    #pragma unroll
    for (int o = 16; o > 0; o >>= 1)
        s += __shfl_xor_sync(0xFFFFFFFFu, s, o);

    __shared__ float warp_sums[8];
    const int lane = threadIdx.x & 31;
    const int wid  = threadIdx.x >> 5;
    if (lane == 0) warp_sums[wid] = s;
    __syncthreads();

    __shared__ bool is_last;
    if (threadIdx.x < 32) {
        float v = (lane < 8) ? warp_sums[lane] : 0.0f;
        #pragma unroll
        for (int o = 4; o > 0; o >>= 1)
            v += __shfl_xor_sync(0xFFFFFFFFu, v, o);
        if (lane == 0) {
            g_partials[blockIdx.x] = v;
            __threadfence();
            unsigned int ticket = atomicAdd(&g_done, 1u);
            is_last = (ticket == gridDim.x - 1);
        }
    }
    __syncthreads();

    // ---- last block: tail reduction over all partials ----
    if (is_last) {
        __threadfence();
        float d = 0.0f;
        for (int i = threadIdx.x; i < (int)gridDim.x; i += 256)
            d += g_partials[i];

        #pragma unroll
        for (int o = 16; o > 0; o >>= 1)
            d += __shfl_xor_sync(0xFFFFFFFFu, d, o);

        if (lane == 0) warp_sums[wid] = d;
        __syncthreads();

        if (threadIdx.x < 32) {
            float v = (lane < 8) ? warp_sums[lane] : 0.0f;
            #pragma unroll
            for (int o = 4; o > 0; o >>= 1)
                v += __shfl_xor_sync(0xFFFFFFFFu, v, o);
            if (lane == 0) {
                out[0] = v * inv_count;
                g_done = 0;   // reset for next graph replay
            }
        }
    }
}

extern "C" void kernel_launch(void* const* d_in, const int* in_sizes, int n_in,
                              void* d_out, int out_size)
{
    const float* x    = (const float*)d_in[0];
    const int*   tg32 = (const int*)d_in[1];
    float* out = (float*)d_out;

    const int B = in_sizes[1];
    const int N = in_sizes[0] / B;

    const float inv_count = (float)(1.0 / ((double)B * (double)N));
    bce_kernel<<<B, 256>>>(x, tg32, out, N, inv_count);
}

// round 9
// speedup vs baseline: 1.5216x; 1.2078x over previous
#include <cuda_runtime.h>
#include <cuda_bf16.h>
#include <cstdint>

#define NBLK 740          // 148 SMs x 5 resident CTAs — one persistent wave
#define STAGE_BYTES 16384
#define STAGE_QUADS 1024

__device__ float        g_partials[NBLK];
__device__ unsigned int g_done = 0;

typedef unsigned long long u64;

__device__ __forceinline__ u64 pk2(float lo, float hi) {
    u64 r;
    asm("mov.b64 %0, {%1, %2};" : "=l"(r) : "f"(lo), "f"(hi));
    return r;
}
__device__ __forceinline__ void upk2(u64 v, float& lo, float& hi) {
    asm("mov.b64 {%0, %1}, %2;" : "=f"(lo), "=f"(hi) : "l"(v));
}
__device__ __forceinline__ u64 ffma2(u64 a, u64 b, u64 c) {
    u64 d;
    asm("fma.rn.f32x2 %0, %1, %2, %3;" : "=l"(d) : "l"(a), "l"(b), "l"(c));
    return d;
}
__device__ __forceinline__ u64 fmul2(u64 a, u64 b) {
    u64 d;
    asm("mul.rn.f32x2 %0, %1, %2;" : "=l"(d) : "l"(a), "l"(b));
    return d;
}
__device__ __forceinline__ u64 fadd2(u64 a, u64 b) {
    u64 d;
    asm("add.rn.f32x2 %0, %1, %2;" : "=l"(d) : "l"(a), "l"(b));
    return d;
}
__device__ __forceinline__ float ex2a(float x) {
    float y;
    asm("ex2.approx.f32 %0, %1;" : "=f"(y) : "f"(x));
    return y;
}
__device__ __forceinline__ uint32_t cvta_s(const void* p) {
    uint32_t a;
    asm("{ .reg .u64 t; cvta.to.shared.u64 t, %1; cvt.u32.u64 %0, t; }"
        : "=r"(a) : "l"(p));
    return a;
}
__device__ __forceinline__ void mbar_init(uint32_t mb, uint32_t cnt) {
    asm volatile("mbarrier.init.shared.b64 [%0], %1;" :: "r"(mb), "r"(cnt) : "memory");
}
__device__ __forceinline__ void mbar_expect_tx(uint32_t mb, uint32_t bytes) {
    asm volatile("mbarrier.arrive.expect_tx.shared.b64 _, [%0], %1;"
                 :: "r"(mb), "r"(bytes) : "memory");
}
__device__ __forceinline__ void bulk_g2s(uint32_t dst_smem, const void* src, uint32_t bytes,
                                         uint32_t mb) {
    asm volatile(
        "cp.async.bulk.shared::cluster.global.mbarrier::complete_tx::bytes "
        "[%0], [%1], %2, [%3];"
        :: "r"(dst_smem), "l"(src), "r"(bytes), "r"(mb) : "memory");
}
__device__ __forceinline__ void mbar_wait(uint32_t mb, uint32_t parity) {
    asm volatile(
        "{\n\t.reg .pred P;\n\t"
        "W_%=:\n\t"
        "mbarrier.try_wait.parity.acquire.cta.shared::cta.b64 P, [%0], %1, 0x989680;\n\t"
        "@P bra.uni D_%=;\n\t"
        "bra.uni W_%=;\n\t"
        "D_%=:\n\t}"
        :: "r"(mb), "r"(parity) : "memory");
}

__global__ __launch_bounds__(256) void bce_kernel(
    const float* __restrict__ x,
    const int* __restrict__ tg32,   // int64 targets viewed as int pairs (LE low word)
    float* __restrict__ out,
    int B, int N, float inv_count)
{
    __shared__ __align__(128) float4 sbuf[2 * STAGE_QUADS];   // 32 KB double buffer
    __shared__ __align__(8)  unsigned long long mbar_store[2];

    const int n4 = N >> 2;

    // log1p(y) on [0,1]: A&S 4.1.43 degree-5 poly, |err| <= 1e-5
    const u64 C0   = pk2( 0.99949556f,  0.99949556f);
    const u64 C1   = pk2(-0.49190896f, -0.49190896f);
    const u64 C2   = pk2( 0.28947478f,  0.28947478f);
    const u64 C3   = pk2(-0.13606275f, -0.13606275f);
    const u64 C4   = pk2( 0.03215845f,  0.03215845f);
    const u64 NL2E = pk2(-1.4426950408889634f, -1.4426950408889634f);
    const u64 SGN2 = 0x8000000080000000ULL;

    u64 accP = 0ULL;   // log1p-poly sums
    u64 accA = 0ULL;   // |x| sums
    u64 accV = 0ULL;   // sign-folded x sums
    float sFix = 0.0f; // partial boundary-quad corrections

    if (n4 == 2048) {
        const int nch = B * 2;   // 16 KB chunks over the whole matrix
        const uint32_t smem = cvta_s(sbuf);
        const uint32_t mb0  = cvta_s(&mbar_store[0]);
        const uint32_t mb1  = cvta_s(&mbar_store[1]);

        if (threadIdx.x == 0) {
            mbar_init(mb0, 1);
            mbar_init(mb1, 1);
        }
        __syncthreads();

        // prime the pipeline: chunks for local iterations 0 and 1
        if (threadIdx.x == 0) {
            const int g0 = blockIdx.x;
            if (g0 < nch) {
                const char* s0 = (const char*)(x + (size_t)(g0 >> 1) * N)
                               + ((g0 & 1) ? STAGE_BYTES : 0);
                mbar_expect_tx(mb0, STAGE_BYTES);
                bulk_g2s(smem, s0, STAGE_BYTES, mb0);
            }
            const int g1 = blockIdx.x + gridDim.x;
            if (g1 < nch) {
                const char* s1 = (const char*)(x + (size_t)(g1 >> 1) * N)
                               + ((g1 & 1) ? STAGE_BYTES : 0);
                mbar_expect_tx(mb1, STAGE_BYTES);
                bulk_g2s(smem + STAGE_BYTES, s1, STAGE_BYTES, mb1);
            }
        }

        int i = 0;
        for (int g = blockIdx.x; g < nch; g += gridDim.x, i++) {
            const int buf = i & 1;
            mbar_wait(buf ? mb1 : mb0, (i >> 1) & 1);

            const int row  = g >> 1;
            const int t    = tg32[row * 2];
            const int q    = t >> 2;
            const int rr   = t & 3;
            const int base = (g & 1) << 10;   // in-row quad index of this chunk's start
            const float4* sb = sbuf + (buf << 10);

            #pragma unroll
            for (int k = 0; k < 4; k++) {
                const int lofs = (int)threadIdx.x + (k << 8);
                const int idx  = base + lofs;
                const float4 v = sb[lofs];
                const float a0 = fabsf(v.x), a1 = fabsf(v.y);
                const float a2 = fabsf(v.z), a3 = fabsf(v.w);
                const u64 a01 = pk2(a0, a1), a23 = pk2(a2, a3);
                // exp(-|x|)
                const u64 u01 = fmul2(a01, NL2E);
                const u64 u23 = fmul2(a23, NL2E);
                float e0, e1, e2, e3;
                upk2(u01, e0, e1); upk2(u23, e2, e3);
                const u64 y01 = pk2(ex2a(e0), ex2a(e1));
                const u64 y23 = pk2(ex2a(e2), ex2a(e3));
                // log1p poly; final FMA folds into accumulator
                u64 p01 = ffma2(y01, C4, C3);
                p01 = ffma2(y01, p01, C2);
                p01 = ffma2(y01, p01, C1);
                p01 = ffma2(y01, p01, C0);
                accP = ffma2(y01, p01, accP);
                u64 p23 = ffma2(y23, C4, C3);
                p23 = ffma2(y23, p23, C2);
                p23 = ffma2(y23, p23, C1);
                p23 = ffma2(y23, p23, C0);
                accP = ffma2(y23, p23, accP);
                // |x| sums
                accA = fadd2(accA, fadd2(a01, a23));
                // sign-folded x sums (branch-free)
                const u64 flip = (idx < q) ? SGN2 : 0ULL;
                accV = fadd2(accV, fadd2(pk2(v.x, v.y) ^ flip, pk2(v.z, v.w) ^ flip));
                // partial boundary quad
                if (idx == q && rr > 0) {
                    float c = v.x;
                    if (rr > 1) c += v.y;
                    if (rr > 2) c += v.z;
                    sFix += c;
                }
            }

            __syncthreads();   // all threads done with this buffer

            if (threadIdx.x == 0) {
                const int gn = g + 2 * gridDim.x;
                if (gn < nch) {
                    const char* sn = (const char*)(x + (size_t)(gn >> 1) * N)
                                   + ((gn & 1) ? STAGE_BYTES : 0);
                    const uint32_t mb = buf ? mb1 : mb0;
                    mbar_expect_tx(mb, STAGE_BYTES);
                    bulk_g2s(smem + buf * STAGE_BYTES, sn, STAGE_BYTES, mb);
                }
            }
        }
    } else {
        // generic correctness path: strided rows, plain global loads
        for (int row = blockIdx.x; row < B; row += gridDim.x) {
            const int t = tg32[row * 2];
            const int q = t >> 2;
            const int rr = t & 3;
            const float4* __restrict__ xr =
                reinterpret_cast<const float4*>(x + (size_t)row * N);
            for (int idx = threadIdx.x; idx < n4; idx += 256) {
                const float4 v = xr[idx];
                const float a0 = fabsf(v.x), a1 = fabsf(v.y);
                const float a2 = fabsf(v.z), a3 = fabsf(v.w);
                const u64 a01 = pk2(a0, a1), a23 = pk2(a2, a3);
                const u64 u01 = fmul2(a01, NL2E);
                const u64 u23 = fmul2(a23, NL2E);
                float e0, e1, e2, e3;
                upk2(u01, e0, e1); upk2(u23, e2, e3);
                const u64 y01 = pk2(ex2a(e0), ex2a(e1));
                const u64 y23 = pk2(ex2a(e2), ex2a(e3));
                u64 p01 = ffma2(y01, C4, C3);
                p01 = ffma2(y01, p01, C2);
                p01 = ffma2(y01, p01, C1);
                p01 = ffma2(y01, p01, C0);
                accP = ffma2(y01, p01, accP);
                u64 p23 = ffma2(y23, C4, C3);
                p23 = ffma2(y23, p23, C2);
                p23 = ffma2(y23, p23, C1);
                p23 = ffma2(y23, p23, C0);
                accP = ffma2(y23, p23, accP);
                accA = fadd2(accA, fadd2(a01, a23));
                const u64 flip = (idx < q) ? SGN2 : 0ULL;
                accV = fadd2(accV, fadd2(pk2(v.x, v.y) ^ flip, pk2(v.z, v.w) ^ flip));
                if (idx == q && rr > 0) {
                    float c = v.x;
                    if (rr > 1) c += v.y;
                    if (rr > 2) c += v.z;
                    sFix += c;
                }
            }
        }
    }

    // s = sum( 0.5*(|x| + sign*x) + log1p(exp(-|x|)) ) - boundary_fixes
    float s;
    {
        float pa, pb, aa, ab, va, vb;
        upk2(accP, pa, pb);
        upk2(accA, aa, ab);
        upk2(accV, va, vb);
        s = 0.5f * ((aa + ab) + (va + vb)) + (pa + pb) - sFix;
    }

    // ---- block reduction (8 warps) ----
    #pragma unroll
    for (int o = 16; o > 0; o >>= 1)
        s += __shfl_xor_sync(0xFFFFFFFFu, s, o);

    __shared__ float warp_sums[8];
    const int lane = threadIdx.x & 31;
    const int wid  = threadIdx.x >> 5;
    if (lane == 0) warp_sums[wid] = s;
    __syncthreads();

    __shared__ bool is_last;
    if (threadIdx.x < 32) {
        float v = (lane < 8) ? warp_sums[lane] : 0.0f;
        #pragma unroll
        for (int o = 4; o > 0; o >>= 1)
            v += __shfl_xor_sync(0xFFFFFFFFu, v, o);
        if (lane == 0) {
            g_partials[blockIdx.x] = v;
            __threadfence();
            unsigned int ticket = atomicAdd(&g_done, 1u);
            is_last = (ticket == gridDim.x - 1);
        }
    }
    __syncthreads();

    // ---- last block: tail reduction over all partials ----
    if (is_last) {
        __threadfence();
        float d = 0.0f;
        for (int i2 = threadIdx.x; i2 < (int)gridDim.x; i2 += 256)
            d += g_partials[i2];

        #pragma unroll
        for (int o = 16; o > 0; o >>= 1)
            d += __shfl_xor_sync(0xFFFFFFFFu, d, o);

        if (lane == 0) warp_sums[wid] = d;
        __syncthreads();

        if (threadIdx.x < 32) {
            float v = (lane < 8) ? warp_sums[lane] : 0.0f;
            #pragma unroll
            for (int o = 4; o > 0; o >>= 1)
                v += __shfl_xor_sync(0xFFFFFFFFu, v, o);
            if (lane == 0) {
                out[0] = v * inv_count;
                g_done = 0;   // reset for next graph replay
            }
        }
    }
}

extern "C" void kernel_launch(void* const* d_in, const int* in_sizes, int n_in,
                              void* d_out, int out_size)
{
    const float* x    = (const float*)d_in[0];
    const int*   tg32 = (const int*)d_in[1];
    float* out = (float*)d_out;

    const int B = in_sizes[1];
    const int N = in_sizes[0] / B;

    const float inv_count = (float)(1.0 / ((double)B * (double)N));
    bce_kernel<<<NBLK, 256>>>(x, tg32, out, B, N, inv_count);
}